// round 3
// baseline (speedup 1.0000x reference)
#include <cuda_runtime.h>
#include <cstdint>

// Problem constants (fixed shapes from reference)
#define NN 8
#define CC 21
#define HH 512
#define WW 512
#define PP (HH * WW)        // 262144 pixels per image
#define SS 16
#define ALPHA_C 10.0f
#define BETA_C  5.0f

#define TPB 256
#define BPN 37              // blocks per image -> 8*37 = 296 blocks = 1 wave @ 2 CTA/SM

// ---------------- global accumulators (device scratch; no allocation) ----------
__device__ float g_P[NN * SS * CC];   // sum of softmax probs per (n,seg,chan)
__device__ float g_L[NN * SS * CC];   // sum of raw logits  per (n,seg,chan)
__device__ float g_cnt[NN * SS];      // pixel count per (n,seg)
__device__ float g_q[NN * SS];        // sum of lnZ per (n,seg)
__device__ int   g_lab[SS];           // segment_max of target per seg (over all n)

// ---------------- fast exp on the FMA pipe (no MUFU, no F2I) -------------------
// 2^f for f in [-0.5, 0.5], deg-5 Taylor (max rel err ~2.4e-6)
__device__ __forceinline__ float poly_exp2(float f) {
    float r = 1.33335581e-3f;
    r = fmaf(r, f, 9.61812911e-3f);
    r = fmaf(r, f, 5.55041087e-2f);
    r = fmaf(r, f, 2.40226507e-1f);
    r = fmaf(r, f, 6.93147181e-1f);
    r = fmaf(r, f, 1.0f);
    return r;
}

// exp(l) = 2^(l*log2e); magic-number round-to-nearest splits integer/fraction.
__device__ __forceinline__ float fexp_e(float l) {
    const float LOG2E = 1.44269504f;
    const float MAGIC = 12582912.0f;   // 1.5 * 2^23
    float t  = fmaf(l, LOG2E, MAGIC);
    int   ib = __float_as_int(t) << 23;           // = i << 23 exactly (i in [-16,16])
    float f  = fmaf(l, LOG2E, -(t - MAGIC));      // fractional part in [-0.5,0.5]
    float r  = poly_exp2(f);
    return __int_as_float(__float_as_int(r) + ib);
}

// 2^x (same trick, plain add)
__device__ __forceinline__ float fexp2(float x) {
    const float MAGIC = 12582912.0f;
    float t  = x + MAGIC;
    int   ib = __float_as_int(t) << 23;
    float f  = x - (t - MAGIC);
    float r  = poly_exp2(f);
    return __int_as_float(__float_as_int(r) + ib);
}

// ---------------- kernels ------------------------------------------------------
__global__ void scl_init_kernel() {
    int i = blockIdx.x * blockDim.x + threadIdx.x;
    if (i < NN * SS * CC) { g_P[i] = 0.0f; g_L[i] = 0.0f; }
    if (i < NN * SS)      { g_cnt[i] = 0.0f; g_q[i] = 0.0f; }
    if (i < SS)           { g_lab[i] = -1; }
}

__global__ __launch_bounds__(TPB, 2)
void scl_main_kernel(const float* __restrict__ logit,
                     const int*   __restrict__ blobs,
                     const int*   __restrict__ target) {
    __shared__ float sP[SS * CC];
    __shared__ float sL[SS * CC];
    __shared__ float sCnt[SS];
    __shared__ float sQ[SS];
    __shared__ int   sLab[SS];

    const int tid = threadIdx.x;
    for (int i = tid; i < SS * CC; i += TPB) { sP[i] = 0.0f; sL[i] = 0.0f; }
    if (tid < SS) { sCnt[tid] = 0.0f; sQ[tid] = 0.0f; sLab[tid] = -1; }
    __syncthreads();

    const int n = blockIdx.y;
    const float2* __restrict__ lg = (const float2*)(logit + (size_t)n * CC * PP);
    const int2*   __restrict__ bb = (const int2*)(blobs  + (size_t)n * PP);
    const int2*   __restrict__ tt = (const int2*)(target + (size_t)n * PP);

    const int G = PP / 2;                       // float2 groups per image
    const float LN2 = 0.69314718f;

    for (int g = blockIdx.x * TPB + tid; g < G; g += BPN * TPB) {
        int2 b2 = bb[g];
        int2 t2 = tt[g];
        int o0 = b2.x * CC;
        int o1 = b2.y * CC;

        float2 e[CC];
        float zx = 0.0f, zy = 0.0f;

        // pass 1: stream logits once, accumulate raw-logit sums + exp + Z
        #pragma unroll
        for (int c = 0; c < CC; c++) {
            float2 l = lg[(size_t)c * (PP / 2) + g];
            atomicAdd(&sL[o0 + c], l.x);
            atomicAdd(&sL[o1 + c], l.y);
            float ex = fexp_e(l.x);
            float ey = fexp_e(l.y);
            zx += ex; zy += ey;
            e[c].x = ex; e[c].y = ey;
        }

        // one MUFU per pixel: log2(Z). 1/Z and lnZ both derived from it.
        float yx = __log2f(zx);
        float yy = __log2f(zy);
        float qx = yx * LN2;
        float qy = yy * LN2;
        float rx = fexp2(-yx);     // 1/Z without division/MUFU.RCP
        float ry = fexp2(-yy);

        // pass 2: accumulate softmax probs (registers only)
        #pragma unroll
        for (int c = 0; c < CC; c++) {
            atomicAdd(&sP[o0 + c], e[c].x * rx);
            atomicAdd(&sP[o1 + c], e[c].y * ry);
        }

        atomicAdd(&sCnt[b2.x], 1.0f);
        atomicAdd(&sCnt[b2.y], 1.0f);
        atomicAdd(&sQ[b2.x], qx);
        atomicAdd(&sQ[b2.y], qy);
        atomicMax(&sLab[b2.x], t2.x);
        atomicMax(&sLab[b2.y], t2.y);
    }

    __syncthreads();
    // flush block-private accumulators to global
    for (int i = tid; i < SS * CC; i += TPB) {
        atomicAdd(&g_P[n * SS * CC + i], sP[i]);
        atomicAdd(&g_L[n * SS * CC + i], sL[i]);
    }
    if (tid < SS) {
        atomicAdd(&g_cnt[n * SS + tid], sCnt[tid]);
        atomicAdd(&g_q[n * SS + tid],   sQ[tid]);
        atomicMax(&g_lab[tid], sLab[tid]);
    }
}

__global__ void scl_final_kernel(float* __restrict__ out) {
    __shared__ float sh_nll[NN * SS];
    __shared__ float sh_kl[NN * SS];
    __shared__ float sh_c[NN * SS];
    __shared__ float sh_pb[SS];

    const int tid = threadIdx.x;       // 128 threads = (n,s) pairs
    const int s   = tid % SS;

    float cnt = g_cnt[tid];
    float nll = 0.0f, kl = 0.0f;
    if (cnt > 0.0f) {
        float inv = 1.0f / cnt;
        float q   = g_q[tid];
        int   lab = g_lab[s];
        const float* Pv = g_P + tid * CC;
        const float* Lv = g_L + tid * CC;
        float ml = 0.0f, msl = 0.0f, mlab = 0.0f;
        #pragma unroll
        for (int c = 0; c < CC; c++) {
            float mean = Pv[c] * inv;
            if (mean > 0.0f) ml += mean * logf(mean);
            msl += mean * (Lv[c] - q);     // slogp_c = Lsum_c - Qsum
            if (c == lab) mlab = mean;
        }
        nll = -logf(mlab);
        kl  = cnt * ml - msl;
    }
    sh_nll[tid] = nll;
    sh_kl[tid]  = kl;
    sh_c[tid]   = cnt;
    __syncthreads();

    if (tid < SS) {
        float la = 0.0f, ks = 0.0f, cs = 0.0f;
        #pragma unroll
        for (int nn = 0; nn < NN; nn++) {
            la += sh_nll[nn * SS + tid];
            ks += sh_kl[nn * SS + tid];
            cs += sh_c[nn * SS + tid];
        }
        la /= (float)NN;
        float dev = ks / ((float)CC * cs);
        sh_pb[tid] = ALPHA_C * la + BETA_C * dev;
    }
    __syncthreads();

    if (tid == 0) {
        float acc = 0.0f;
        #pragma unroll
        for (int ss = 0; ss < SS; ss++) acc += sh_pb[ss];
        out[0] = acc / (float)SS;
    }
}

// ---------------- launch -------------------------------------------------------
extern "C" void kernel_launch(void* const* d_in, const int* in_sizes, int n_in,
                              void* d_out, int out_size) {
    const float* logit  = (const float*)d_in[0];
    const int*   blobs  = (const int*)d_in[1];
    const int*   target = (const int*)d_in[2];
    float*       out    = (float*)d_out;

    scl_init_kernel<<<(NN * SS * CC + 255) / 256, 256>>>();
    dim3 grid(BPN, NN);
    scl_main_kernel<<<grid, TPB>>>(logit, blobs, target);
    scl_final_kernel<<<1, NN * SS>>>(out);
}

// round 4
// speedup vs baseline: 2.6802x; 2.6802x over previous
#include <cuda_runtime.h>
#include <cstdint>

// Problem constants (fixed shapes from reference)
#define NN 8
#define CC 21
#define HH 512
#define WW 512
#define PP (HH * WW)        // 262144 pixels per image
#define GG (PP / 2)         // 131072 float2 pixel-pairs per image
#define SS 16
#define ALPHA_C 10.0f
#define BETA_C  5.0f

#define TPB 256
#define BPN 74              // blocks per image -> 8*74 = 592 blocks = 1 wave @ 4 CTA/SM
#define TILES (GG / TPB)    // 512 tiles of 256 pairs per image (exact)

#define NSTREAM 22          // 21 channel streams + 1 meta stream (cnt/q/labels)
#define NREP 8              // accumulator replicas
#define CHUNK 32            // pairs per reader (32 * 8B = 256B, line-aligned)
#define NREAD (NSTREAM * NREP)  // 176 reader threads

// ---------------- global accumulators (device scratch; no allocation) ----------
__device__ float g_P[NN * SS * CC];   // sum of softmax probs per (n,seg,chan)
__device__ float g_L[NN * SS * CC];   // sum of raw logits  per (n,seg,chan)
__device__ float g_cnt[NN * SS];      // pixel count per (n,seg)
__device__ float g_q[NN * SS];        // sum of lnZ per (n,seg)
__device__ int   g_lab[SS];           // segment_max of target per seg (over all n)

// ---------------- fast exp on the FMA pipe (no MUFU, no F2I) -------------------
// 2^f for f in [-0.5, 0.5], deg-5 Taylor (max rel err ~2.4e-6)
__device__ __forceinline__ float poly_exp2(float f) {
    float r = 1.33335581e-3f;
    r = fmaf(r, f, 9.61812911e-3f);
    r = fmaf(r, f, 5.55041087e-2f);
    r = fmaf(r, f, 2.40226507e-1f);
    r = fmaf(r, f, 6.93147181e-1f);
    r = fmaf(r, f, 1.0f);
    return r;
}

// exp(l) = 2^(l*log2e); magic-number round-to-nearest splits integer/fraction.
__device__ __forceinline__ float fexp_e(float l) {
    const float LOG2E = 1.44269504f;
    const float MAGIC = 12582912.0f;   // 1.5 * 2^23
    float t  = fmaf(l, LOG2E, MAGIC);
    int   ib = __float_as_int(t) << 23;           // = i << 23 exactly
    float f  = fmaf(l, LOG2E, -(t - MAGIC));      // fractional part in [-0.5,0.5]
    float r  = poly_exp2(f);
    return __int_as_float(__float_as_int(r) + ib);
}

// 2^x (same trick, plain add)
__device__ __forceinline__ float fexp2(float x) {
    const float MAGIC = 12582912.0f;
    float t  = x + MAGIC;
    int   ib = __float_as_int(t) << 23;
    float f  = x - (t - MAGIC);
    float r  = poly_exp2(f);
    return __int_as_float(__float_as_int(r) + ib);
}

// ---------------- kernels ------------------------------------------------------
__global__ void scl_init_kernel() {
    int i = blockIdx.x * blockDim.x + threadIdx.x;
    if (i < NN * SS * CC) { g_P[i] = 0.0f; g_L[i] = 0.0f; }
    if (i < NN * SS)      { g_cnt[i] = 0.0f; g_q[i] = 0.0f; }
    if (i < SS)           { g_lab[i] = -1; }
}

__global__ __launch_bounds__(TPB, 4)
void scl_main_kernel(const float* __restrict__ logit,
                     const int*   __restrict__ blobs,
                     const int*   __restrict__ target) {
    // [seg][reader_tid] private accumulators: .x = p-sum (or q-sum), .y = l-sum (or cnt)
    __shared__ float2 sAcc[SS][TPB];          // 32 KB, conflict-free (tid contiguous)
    __shared__ float4 sRQ[TPB];               // (rx, ry, qx, qy) per pair
    __shared__ int2   sB[TPB];                // blob ids per pair
    __shared__ int2   sT[TPB];                // targets per pair
    __shared__ int    sLab[NREP * SS];        // per-replica label max

    const int tid = threadIdx.x;
    const int n   = blockIdx.y;

    #pragma unroll
    for (int s = 0; s < SS; s++) sAcc[s][tid] = make_float2(0.0f, 0.0f);
    if (tid < NREP * SS) sLab[tid] = -1;

    const float2* __restrict__ lg = (const float2*)(logit + (size_t)n * CC * PP);
    const int2*   __restrict__ bb = (const int2*)(blobs  + (size_t)n * PP);
    const int2*   __restrict__ tt = (const int2*)(target + (size_t)n * PP);

    const int stream = tid % NSTREAM;
    const int rep    = tid / NSTREAM;
    const float LN2  = 0.69314718f;

    for (int tix = blockIdx.x; tix < TILES; tix += BPN) {
        __syncthreads();   // previous tile's readers done with sRQ/sB/sT (and covers init)

        // ---- producer phase: stream logits (DRAM), compute Z per pixel ----
        const int g = tix * TPB + tid;
        float zx = 0.0f, zy = 0.0f;
        #pragma unroll
        for (int c = 0; c < CC; c++) {
            float2 l = lg[(size_t)c * GG + g];
            zx += fexp_e(l.x);
            zy += fexp_e(l.y);
        }
        float yx = __log2f(zx);
        float yy = __log2f(zy);
        sRQ[tid] = make_float4(fexp2(-yx), fexp2(-yy), yx * LN2, yy * LN2);
        sB[tid]  = bb[g];
        sT[tid]  = tt[g];
        __syncthreads();

        // ---- reader phase: re-read channel columns from L2, accumulate privately ----
        if (tid < NREAD) {
            const int p0 = rep * CHUNK;
            if (stream < CC) {
                const float2* __restrict__ col =
                    lg + (size_t)stream * GG + (size_t)tix * TPB + p0;
                #pragma unroll 4
                for (int i = 0; i < CHUNK; i++) {
                    const int p = p0 + i;
                    float2 l  = col[i];          // L2 hit (just streamed by producer)
                    float4 rq = sRQ[p];
                    int2   b  = sB[p];
                    float  px = fexp_e(l.x) * rq.x;
                    float  py = fexp_e(l.y) * rq.y;
                    if (b.x == b.y) {
                        float2 a = sAcc[b.x][tid];
                        a.x += px + py;  a.y += l.x + l.y;
                        sAcc[b.x][tid] = a;
                    } else {
                        float2 a0 = sAcc[b.x][tid];
                        a0.x += px;  a0.y += l.x;
                        sAcc[b.x][tid] = a0;
                        float2 a1 = sAcc[b.y][tid];
                        a1.x += py;  a1.y += l.y;
                        sAcc[b.y][tid] = a1;
                    }
                }
            } else {
                // meta stream: (qsum, cnt) + label max
                #pragma unroll 4
                for (int i = 0; i < CHUNK; i++) {
                    const int p = p0 + i;
                    float4 rq = sRQ[p];
                    int2   b  = sB[p];
                    int2   t  = sT[p];
                    if (b.x == b.y) {
                        float2 a = sAcc[b.x][tid];
                        a.x += rq.z + rq.w;  a.y += 2.0f;
                        sAcc[b.x][tid] = a;
                    } else {
                        float2 a0 = sAcc[b.x][tid];
                        a0.x += rq.z;  a0.y += 1.0f;
                        sAcc[b.x][tid] = a0;
                        float2 a1 = sAcc[b.y][tid];
                        a1.x += rq.w;  a1.y += 1.0f;
                        sAcc[b.y][tid] = a1;
                    }
                    int l0 = sLab[rep * SS + b.x];
                    if (t.x > l0) sLab[rep * SS + b.x] = t.x;
                    int l1 = sLab[rep * SS + b.y];
                    if (t.y > l1) sLab[rep * SS + b.y] = t.y;
                }
            }
        }
    }
    __syncthreads();

    // ---- flush: reduce replicas, one global atomic per (seg, stream) ----
    for (int i = tid; i < NSTREAM * SS; i += TPB) {
        const int st = i % NSTREAM;
        const int s  = i / NSTREAM;
        float sx = 0.0f, sy = 0.0f;
        #pragma unroll
        for (int r = 0; r < NREP; r++) {
            float2 a = sAcc[s][r * NSTREAM + st];
            sx += a.x;  sy += a.y;
        }
        if (st < CC) {
            atomicAdd(&g_P[(n * SS + s) * CC + st], sx);
            atomicAdd(&g_L[(n * SS + s) * CC + st], sy);
        } else {
            atomicAdd(&g_q[n * SS + s],   sx);
            atomicAdd(&g_cnt[n * SS + s], sy);
        }
    }
    if (tid < NREP * SS) {
        atomicMax(&g_lab[tid & (SS - 1)], sLab[tid]);
    }
}

__global__ void scl_final_kernel(float* __restrict__ out) {
    __shared__ float sh_nll[NN * SS];
    __shared__ float sh_kl[NN * SS];
    __shared__ float sh_c[NN * SS];
    __shared__ float sh_pb[SS];

    const int tid = threadIdx.x;       // 128 threads = (n,s) pairs
    const int s   = tid % SS;

    float cnt = g_cnt[tid];
    float nll = 0.0f, kl = 0.0f;
    if (cnt > 0.0f) {
        float inv = 1.0f / cnt;
        float q   = g_q[tid];
        int   lab = g_lab[s];
        const float* Pv = g_P + tid * CC;
        const float* Lv = g_L + tid * CC;
        float ml = 0.0f, msl = 0.0f, mlab = 0.0f;
        #pragma unroll
        for (int c = 0; c < CC; c++) {
            float mean = Pv[c] * inv;
            if (mean > 0.0f) ml += mean * logf(mean);
            msl += mean * (Lv[c] - q);     // slogp_c = Lsum_c - Qsum
            if (c == lab) mlab = mean;
        }
        nll = -logf(mlab);
        kl  = cnt * ml - msl;
    }
    sh_nll[tid] = nll;
    sh_kl[tid]  = kl;
    sh_c[tid]   = cnt;
    __syncthreads();

    if (tid < SS) {
        float la = 0.0f, ks = 0.0f, cs = 0.0f;
        #pragma unroll
        for (int nn = 0; nn < NN; nn++) {
            la += sh_nll[nn * SS + tid];
            ks += sh_kl[nn * SS + tid];
            cs += sh_c[nn * SS + tid];
        }
        la /= (float)NN;
        float dev = ks / ((float)CC * cs);
        sh_pb[tid] = ALPHA_C * la + BETA_C * dev;
    }
    __syncthreads();

    if (tid == 0) {
        float acc = 0.0f;
        #pragma unroll
        for (int ss = 0; ss < SS; ss++) acc += sh_pb[ss];
        out[0] = acc / (float)SS;
    }
}

// ---------------- launch -------------------------------------------------------
extern "C" void kernel_launch(void* const* d_in, const int* in_sizes, int n_in,
                              void* d_out, int out_size) {
    const float* logit  = (const float*)d_in[0];
    const int*   blobs  = (const int*)d_in[1];
    const int*   target = (const int*)d_in[2];
    float*       out    = (float*)d_out;

    scl_init_kernel<<<(NN * SS * CC + 255) / 256, 256>>>();
    dim3 grid(BPN, NN);
    scl_main_kernel<<<grid, TPB>>>(logit, blobs, target);
    scl_final_kernel<<<1, NN * SS>>>(out);
}